// round 5
// baseline (speedup 1.0000x reference)
#include <cuda_runtime.h>
#include <cuda_bf16.h>
#include <cstdint>

// ---------------------------------------------------------------------------
// QuantizedLinear via legacy mma.sync IMMA (compute_103 base target; tcgen05
// is 'a'-gated and rejected by this harness's ptxas invocation).
//   q_in = clip(rint(x/s_in)+zp_in) ; acc = q_in·W^T + bias ;
//   out  = (float)clip(rint((float)acc/s_out)+zp_out)        [f32 out buffer]
// M=8192, K=4096, N=4096.
// GEMM v2: 128x128 CTA tile, BK=128B, 2-stage cp.async, ldmatrix.x4 fragment
// loads, 8 warps (2x4), warp tile 64x32, mma.m16n8k32.s8.s8.s32.
// 3 launches per call so ncu (-s 5 -c 1) lands on the GEMM.
// ---------------------------------------------------------------------------

#define MAX_M 8192
#define MAX_K 4096
#define MAX_N 8192

__device__ int8_t g_qin[(size_t)MAX_M * MAX_K];   // quantized input [M,K]
__device__ int8_t g_w[(size_t)MAX_N * MAX_K];     // repacked weight [N,K]
__device__ int    g_bias[MAX_N];

// ---------------- helpers ---------------------------------------------------
__device__ __forceinline__ uint32_t smem_u32(const void* p) {
    uint32_t a;
    asm("{ .reg .u64 t; cvta.to.shared.u64 t, %1; cvt.u32.u64 %0, t; }"
        : "=r"(a) : "l"(p));
    return a;
}
__device__ __forceinline__ float read_scale_f(const void* p, float lo, float hi) {
    float f = *(const float*)p;
    if (isfinite(f) && f > lo && f < hi) return f;
    return (float)(*(const double*)p);
}
__device__ __forceinline__ int clamp_i8(int v) { return max(-128, min(127, v)); }

__device__ __forceinline__ void cp_async16(uint32_t dst, const void* src) {
    asm volatile("cp.async.cg.shared.global [%0], [%1], 16;"
                 :: "r"(dst), "l"(src) : "memory");
}
#define CP_COMMIT() asm volatile("cp.async.commit_group;" ::: "memory")

__device__ __forceinline__ void mma_s8(int* d, const int* a, const int* b) {
    asm volatile(
        "mma.sync.aligned.m16n8k32.row.col.s32.s8.s8.s32 "
        "{%0,%1,%2,%3}, {%4,%5,%6,%7}, {%8,%9}, {%0,%1,%2,%3};"
        : "+r"(d[0]), "+r"(d[1]), "+r"(d[2]), "+r"(d[3])
        : "r"(a[0]), "r"(a[1]), "r"(a[2]), "r"(a[3]),
          "r"(b[0]), "r"(b[1]));
}
__device__ __forceinline__ void ldm_x4(uint32_t addr, int& r0, int& r1,
                                       int& r2, int& r3) {
    asm volatile("ldmatrix.sync.aligned.m8n8.x4.shared.b16 {%0,%1,%2,%3}, [%4];"
                 : "=r"(r0), "=r"(r1), "=r"(r2), "=r"(r3) : "r"(addr));
}

// ---------------- launch 1: quantize input ----------------------------------
__global__ void quant_kernel(const float4* __restrict__ x,
                             const void* __restrict__ s_p,
                             const int* __restrict__ zp_p, int n4) {
    int i = blockIdx.x * blockDim.x + threadIdx.x;
    if (i >= n4) return;
    float s = read_scale_f(s_p, 1e-6f, 1e3f);
    int zp = __ldg(zp_p);
    float4 v = x[i];
    char4 q;
    q.x = (char)clamp_i8((int)rintf(v.x / s) + zp);
    q.y = (char)clamp_i8((int)rintf(v.y / s) + zp);
    q.z = (char)clamp_i8((int)rintf(v.z / s) + zp);
    q.w = (char)clamp_i8((int)rintf(v.w / s) + zp);
    ((char4*)g_qin)[i] = q;
}

// ---------------- launch 2: fused weight+bias repack (inline dtype detect) --
__global__ void convert_kernel(const void* __restrict__ w,
                               const void* __restrict__ b,
                               int wn4, int n) {
    int i = blockIdx.x * blockDim.x + threadIdx.x;

    if (i < wn4) {
        // detect weight dtype from first 16 words (uniform, L1-broadcast)
        const int* wi = (const int*)w; const float* wf = (const float*)w;
        bool i32 = true, f32 = true;
#pragma unroll
        for (int k = 0; k < 16; k++) {
            int v = __ldg(&wi[k]);
            if (v < -128 || v > 127) i32 = false;
            float f = __ldg(&wf[k]);
            if (!isfinite(f) || f != rintf(f) || fabsf(f) > 128.0f) f32 = false;
        }
        char4 q;
        if (i32) {
            int4 v = ((const int4*)w)[i];
            q.x = (char)v.x; q.y = (char)v.y; q.z = (char)v.z; q.w = (char)v.w;
        } else if (f32) {
            float4 v = ((const float4*)w)[i];
            q.x = (char)(int)rintf(v.x); q.y = (char)(int)rintf(v.y);
            q.z = (char)(int)rintf(v.z); q.w = (char)(int)rintf(v.w);
        } else {
            q = ((const char4*)w)[i];
        }
        ((char4*)g_w)[i] = q;
    } else {
        int j = i - wn4;
        if (j < n) {
            const int* bi = (const int*)b; const float* bf = (const float*)b;
            bool i32 = true;
#pragma unroll
            for (int k = 0; k < 16; k++)
                if (__ldg(&bi[k]) < -32768 || __ldg(&bi[k]) > 32767) i32 = false;
            g_bias[j] = i32 ? ((const int*)b)[j] : (int)rintf(((const float*)b)[j]);
        }
    }
}

// ---------------- launch 3: IMMA GEMM ---------------------------------------
#define BM 128
#define BN 128
#define BKB 128          // K bytes per stage
#define PAD_ROW 144      // 128 data + 16 pad -> ldmatrix conflict-free
#define STAGE_BYTES ((BM + BN) * PAD_ROW)

extern __shared__ int8_t dsmem[];

__global__ __launch_bounds__(256, 2)
void gemm_imma_kernel(float* __restrict__ C, int M, int N, int K,
                      const void* __restrict__ os_p,
                      const int* __restrict__ ozp_p) {
    const int t   = threadIdx.x;
    const int wid = t >> 5;
    const int lid = t & 31;
    const int g   = lid >> 2;      // groupID 0..7
    const int t4  = lid & 3;
    const int wm  = wid >> 2;      // 0..1
    const int wn  = wid & 3;       // 0..3
    const int bm  = blockIdx.y * BM;
    const int bn  = blockIdx.x * BN;

    const uint32_t sA0 = smem_u32(dsmem);
    const uint32_t sB0 = sA0 + BM * PAD_ROW;

    const int8_t* gA = g_qin + (size_t)bm * K;
    const int8_t* gB = g_w   + (size_t)bn * K;

    int acc[4][4][4];
#pragma unroll
    for (int i = 0; i < 4; i++)
#pragma unroll
        for (int j = 0; j < 4; j++)
#pragma unroll
            for (int r = 0; r < 4; r++) acc[i][j][r] = 0;

    // cp.async tile loader: 1024 16B chunks per side, 4 per thread per side
    auto load_tiles = [&](int stage, int k0) {
        uint32_t so = stage * STAGE_BYTES;
#pragma unroll
        for (int l = 0; l < 4; l++) {
            int c   = t + l * 256;     // 0..1023
            int row = c >> 3;          // 0..127
            int seg = (c & 7) * 16;    // 0..112
            uint32_t doff = so + row * PAD_ROW + seg;
            const size_t goff = (size_t)row * K + k0 + seg;
            cp_async16(sA0 + doff, gA + goff);
            cp_async16(sB0 + doff, gB + goff);
        }
        CP_COMMIT();
    };

    // ldmatrix per-thread addressing (x4: matrices row0-7/row8-15 x k0-15/k16-31)
    const int lm_row = (lid & 7) + ((lid >> 3) & 1) * 8;
    const int lm_col = (lid >> 4) * 16;
    uint32_t a_base[4], b_base[2];
#pragma unroll
    for (int mt = 0; mt < 4; mt++)
        a_base[mt] = sA0 + (wm * 64 + mt * 16 + lm_row) * PAD_ROW + lm_col;
#pragma unroll
    for (int p = 0; p < 2; p++)
        b_base[p] = sB0 + (wn * 32 + p * 16 + lm_row) * PAD_ROW + lm_col;

    const int niter = K / BKB;
    load_tiles(0, 0);

    for (int it = 0; it < niter; it++) {
        if (it + 1 < niter) {
            load_tiles((it + 1) & 1, (it + 1) * BKB);
            asm volatile("cp.async.wait_group 1;" ::: "memory");
        } else {
            asm volatile("cp.async.wait_group 0;" ::: "memory");
        }
        __syncthreads();

        const uint32_t so = (uint32_t)(it & 1) * STAGE_BYTES;
#pragma unroll
        for (int ks = 0; ks < 4; ks++) {
            const uint32_t kb = so + ks * 32;
            int af[4][4], bf[4][2];
#pragma unroll
            for (int mt = 0; mt < 4; mt++)
                ldm_x4(a_base[mt] + kb, af[mt][0], af[mt][1], af[mt][2], af[mt][3]);
#pragma unroll
            for (int p = 0; p < 2; p++) {
                int r0, r1, r2, r3;
                ldm_x4(b_base[p] + kb, r0, r1, r2, r3);
                bf[2 * p][0]     = r0;  // n 0-7 of pair, k0-15
                bf[2 * p + 1][0] = r1;  // n 8-15, k0-15
                bf[2 * p][1]     = r2;  // n 0-7, k16-31
                bf[2 * p + 1][1] = r3;  // n 8-15, k16-31
            }
#pragma unroll
            for (int mt = 0; mt < 4; mt++)
#pragma unroll
                for (int nt = 0; nt < 4; nt++)
                    mma_s8(acc[mt][nt], af[mt], bf[nt]);
        }
        __syncthreads();
    }

    // ---------------- epilogue ----------------------------------------------
    const float os = read_scale_f(os_p, 1e-3f, 1e9f);
    const int ozp = __ldg(ozp_p);

#pragma unroll
    for (int mt = 0; mt < 4; mt++) {
        const int row0 = bm + wm * 64 + mt * 16 + g;
#pragma unroll
        for (int nt = 0; nt < 4; nt++) {
            const int col0 = bn + wn * 32 + nt * 8 + t4 * 2;
            const int b0 = g_bias[col0];
            const int b1 = g_bias[col0 + 1];
            float2 lo, hi;
            lo.x = (float)clamp_i8((int)rintf((float)(acc[mt][nt][0] + b0) / os) + ozp);
            lo.y = (float)clamp_i8((int)rintf((float)(acc[mt][nt][1] + b1) / os) + ozp);
            hi.x = (float)clamp_i8((int)rintf((float)(acc[mt][nt][2] + b0) / os) + ozp);
            hi.y = (float)clamp_i8((int)rintf((float)(acc[mt][nt][3] + b1) / os) + ozp);
            *(float2*)&C[(size_t)row0 * N + col0]       = lo;
            *(float2*)&C[(size_t)(row0 + 8) * N + col0] = hi;
        }
    }
}

// ---------------------------------------------------------------------------
extern "C" void kernel_launch(void* const* d_in, const int* in_sizes, int n_in,
                              void* d_out, int out_size) {
    const float* input  = (const float*)d_in[0];
    const void*  weight = d_in[1];
    const void*  bias   = d_in[2];
    const void*  in_s   = d_in[3];
    const int*   in_zp  = (const int*)d_in[4];
    const void*  out_s  = d_in[5];
    const int*   out_zp = (const int*)d_in[6];

    const int N = in_sizes[2];
    const int K = in_sizes[1] / N;
    const int M = in_sizes[0] / K;

    float* out = (float*)d_out;

    // launch 1: quantize input
    int n4 = (M * K) / 4;
    quant_kernel<<<(n4 + 255) / 256, 256>>>((const float4*)input, in_s, in_zp, n4);

    // launch 2: fused weight + bias repack
    int wn4 = (N * K) / 4;
    int tot = wn4 + N;
    convert_kernel<<<(tot + 255) / 256, 256>>>(weight, bias, wn4, N);

    // launch 3: GEMM (dynamic smem: 2 stages x 72KB total)
    static int smem_set = 0;
    cudaFuncSetAttribute(gemm_imma_kernel,
                         cudaFuncAttributeMaxDynamicSharedMemorySize,
                         2 * STAGE_BYTES);
    (void)smem_set;
    dim3 grid(N / BN, M / BM);
    gemm_imma_kernel<<<grid, 256, 2 * STAGE_BYTES>>>(out, M, N, K, out_s, out_zp);
}

// round 6
// speedup vs baseline: 2.1596x; 2.1596x over previous
#include <cuda_runtime.h>
#include <cuda_bf16.h>
#include <cstdint>

// ---------------------------------------------------------------------------
// QuantizedLinear — bf16 HMMA probe (compute_103 target; tcgen05 is 'a'-gated).
// Rationale: s8 mma.sync measured at dp4a-pipe rate (~256 MAC/cyc/SM) -> it is
// emulated. Testing whether bf16 mma.sync hits native HW instead.
// Exactness: q_in,w in [-128,127] exact in bf16; all partial sums are integers
// < 2^24 so every f32 add is exact -> accumulator bit-identical to int path.
//   q_in = clip(rint(x/s_in)+zp_in) ; acc = q_in·W^T + bias ;
//   out  = (float)clip(rint((float)acc/s_out)+zp_out)        [f32 out buffer]
// M=8192, K=4096, N=4096.
// ---------------------------------------------------------------------------

#define MAX_M 8192
#define MAX_K 4096
#define MAX_N 8192

__device__ __nv_bfloat16 g_qin[(size_t)MAX_M * MAX_K];  // quantized input [M,K]
__device__ __nv_bfloat16 g_w[(size_t)MAX_N * MAX_K];    // repacked weight [N,K]
__device__ int           g_bias[MAX_N];

// ---------------- helpers ---------------------------------------------------
__device__ __forceinline__ uint32_t smem_u32(const void* p) {
    uint32_t a;
    asm("{ .reg .u64 t; cvta.to.shared.u64 t, %1; cvt.u32.u64 %0, t; }"
        : "=r"(a) : "l"(p));
    return a;
}
__device__ __forceinline__ float read_scale_f(const void* p, float lo, float hi) {
    float f = *(const float*)p;
    if (isfinite(f) && f > lo && f < hi) return f;
    return (float)(*(const double*)p);
}
__device__ __forceinline__ int clamp_i8(int v) { return max(-128, min(127, v)); }

__device__ __forceinline__ void cp_async16(uint32_t dst, const void* src) {
    asm volatile("cp.async.cg.shared.global [%0], [%1], 16;"
                 :: "r"(dst), "l"(src) : "memory");
}
#define CP_COMMIT() asm volatile("cp.async.commit_group;" ::: "memory")

__device__ __forceinline__ void mma_bf16(float* d, const int* a, const int* b) {
    asm volatile(
        "mma.sync.aligned.m16n8k16.row.col.f32.bf16.bf16.f32 "
        "{%0,%1,%2,%3}, {%4,%5,%6,%7}, {%8,%9}, {%0,%1,%2,%3};"
        : "+f"(d[0]), "+f"(d[1]), "+f"(d[2]), "+f"(d[3])
        : "r"(a[0]), "r"(a[1]), "r"(a[2]), "r"(a[3]),
          "r"(b[0]), "r"(b[1]));
}
__device__ __forceinline__ void ldm_x4(uint32_t addr, int& r0, int& r1,
                                       int& r2, int& r3) {
    asm volatile("ldmatrix.sync.aligned.m8n8.x4.shared.b16 {%0,%1,%2,%3}, [%4];"
                 : "=r"(r0), "=r"(r1), "=r"(r2), "=r"(r3) : "r"(addr));
}

// ---------------- launch 1: quantize input -> bf16 --------------------------
__global__ void quant_kernel(const float4* __restrict__ x,
                             const void* __restrict__ s_p,
                             const int* __restrict__ zp_p, int n4) {
    int i = blockIdx.x * blockDim.x + threadIdx.x;
    if (i >= n4) return;
    float s = read_scale_f(s_p, 1e-6f, 1e3f);
    int zp = __ldg(zp_p);
    float4 v = x[i];
    __nv_bfloat16 q[4];
    q[0] = __float2bfloat16_rn((float)clamp_i8((int)rintf(v.x / s) + zp));
    q[1] = __float2bfloat16_rn((float)clamp_i8((int)rintf(v.y / s) + zp));
    q[2] = __float2bfloat16_rn((float)clamp_i8((int)rintf(v.z / s) + zp));
    q[3] = __float2bfloat16_rn((float)clamp_i8((int)rintf(v.w / s) + zp));
    ((uint2*)g_qin)[i] = *(const uint2*)q;
}

// ---------------- launch 2: weight+bias repack -> bf16/int ------------------
__global__ void convert_kernel(const void* __restrict__ w,
                               const void* __restrict__ b,
                               int wn4, int n) {
    int i = blockIdx.x * blockDim.x + threadIdx.x;

    if (i < wn4) {
        const int* wi = (const int*)w; const float* wf = (const float*)w;
        bool i32 = true, f32 = true;
#pragma unroll
        for (int k = 0; k < 16; k++) {
            int v = __ldg(&wi[k]);
            if (v < -128 || v > 127) i32 = false;
            float f = __ldg(&wf[k]);
            if (!isfinite(f) || f != rintf(f) || fabsf(f) > 128.0f) f32 = false;
        }
        float v0, v1, v2, v3;
        if (i32) {
            int4 v = ((const int4*)w)[i];
            v0 = (float)v.x; v1 = (float)v.y; v2 = (float)v.z; v3 = (float)v.w;
        } else if (f32) {
            float4 v = ((const float4*)w)[i];
            v0 = rintf(v.x); v1 = rintf(v.y); v2 = rintf(v.z); v3 = rintf(v.w);
        } else {
            char4 v = ((const char4*)w)[i];
            v0 = (float)v.x; v1 = (float)v.y; v2 = (float)v.z; v3 = (float)v.w;
        }
        __nv_bfloat16 q[4];
        q[0] = __float2bfloat16_rn(v0); q[1] = __float2bfloat16_rn(v1);
        q[2] = __float2bfloat16_rn(v2); q[3] = __float2bfloat16_rn(v3);
        ((uint2*)g_w)[i] = *(const uint2*)q;
    } else {
        int j = i - wn4;
        if (j < n) {
            const int* bi = (const int*)b; const float* bf = (const float*)b;
            bool i32 = true;
#pragma unroll
            for (int k = 0; k < 16; k++)
                if (__ldg(&bi[k]) < -32768 || __ldg(&bi[k]) > 32767) i32 = false;
            g_bias[j] = i32 ? ((const int*)b)[j] : (int)rintf(((const float*)b)[j]);
        }
    }
}

// ---------------- launch 3: bf16 HMMA GEMM ----------------------------------
#define BM 128
#define BN 128
#define BKE 64           // K elements per stage (= 128 bytes per row)
#define PAD_ROW 144      // 128 data bytes + 16 pad -> ldmatrix conflict-free
#define STAGE_BYTES ((BM + BN) * PAD_ROW)

extern __shared__ int8_t dsmem[];

__global__ __launch_bounds__(256, 2)
void gemm_bf16_kernel(float* __restrict__ C, int M, int N, int K,
                      const void* __restrict__ os_p,
                      const int* __restrict__ ozp_p) {
    const int t   = threadIdx.x;
    const int wid = t >> 5;
    const int lid = t & 31;
    const int g   = lid >> 2;      // groupID 0..7
    const int t4  = lid & 3;
    const int wm  = wid >> 2;      // 0..1
    const int wn  = wid & 3;       // 0..3
    const int bm  = blockIdx.y * BM;
    const int bn  = blockIdx.x * BN;

    const uint32_t sA0 = smem_u32(dsmem);
    const uint32_t sB0 = sA0 + BM * PAD_ROW;

    const size_t Kb = (size_t)K * 2;   // row stride in bytes
    const char* gA = (const char*)g_qin + (size_t)bm * Kb;
    const char* gB = (const char*)g_w   + (size_t)bn * Kb;

    float acc[4][4][4];
#pragma unroll
    for (int i = 0; i < 4; i++)
#pragma unroll
        for (int j = 0; j < 4; j++)
#pragma unroll
            for (int r = 0; r < 4; r++) acc[i][j][r] = 0.0f;

    // tile loader: 128 rows x 128B per side -> 1024 chunks, 4/thread/side
    auto load_tiles = [&](int stage, int kbyte0) {
        uint32_t so = stage * STAGE_BYTES;
#pragma unroll
        for (int l = 0; l < 4; l++) {
            int c   = t + l * 256;     // 0..1023
            int row = c >> 3;          // 0..127
            int seg = (c & 7) * 16;    // 0..112 bytes
            uint32_t doff = so + row * PAD_ROW + seg;
            const size_t goff = (size_t)row * Kb + kbyte0 + seg;
            cp_async16(sA0 + doff, gA + goff);
            cp_async16(sB0 + doff, gB + goff);
        }
        CP_COMMIT();
    };

    // ldmatrix addressing: row = (lid&7)+((lid>>3)&1)*8 ; byte col = (lid>>4)*16
    const int lm_row = (lid & 7) + ((lid >> 3) & 1) * 8;
    const int lm_col = (lid >> 4) * 16;
    uint32_t a_base[4], b_base[2];
#pragma unroll
    for (int mt = 0; mt < 4; mt++)
        a_base[mt] = sA0 + (wm * 64 + mt * 16 + lm_row) * PAD_ROW + lm_col;
#pragma unroll
    for (int p = 0; p < 2; p++)
        b_base[p] = sB0 + (wn * 32 + p * 16 + lm_row) * PAD_ROW + lm_col;

    const int niter = K / BKE;          // 64
    load_tiles(0, 0);

    for (int it = 0; it < niter; it++) {
        if (it + 1 < niter) {
            load_tiles((it + 1) & 1, (it + 1) * (BKE * 2));
            asm volatile("cp.async.wait_group 1;" ::: "memory");
        } else {
            asm volatile("cp.async.wait_group 0;" ::: "memory");
        }
        __syncthreads();

        const uint32_t so = (uint32_t)(it & 1) * STAGE_BYTES;
#pragma unroll
        for (int ks = 0; ks < 4; ks++) {          // 4 x k16 steps (32B each)
            const uint32_t kb = so + ks * 32;
            int af[4][4], bf[4][2];
#pragma unroll
            for (int mt = 0; mt < 4; mt++)
                ldm_x4(a_base[mt] + kb, af[mt][0], af[mt][1], af[mt][2], af[mt][3]);
#pragma unroll
            for (int p = 0; p < 2; p++) {
                int r0, r1, r2, r3;
                ldm_x4(b_base[p] + kb, r0, r1, r2, r3);
                bf[2 * p][0]     = r0;  // n 0-7,  k0-7
                bf[2 * p + 1][0] = r1;  // n 8-15, k0-7
                bf[2 * p][1]     = r2;  // n 0-7,  k8-15
                bf[2 * p + 1][1] = r3;  // n 8-15, k8-15
            }
#pragma unroll
            for (int mt = 0; mt < 4; mt++)
#pragma unroll
                for (int nt = 0; nt < 4; nt++)
                    mma_bf16(acc[mt][nt], af[mt], bf[nt]);
        }
        __syncthreads();
    }

    // ---------------- epilogue ----------------------------------------------
    const float os = read_scale_f(os_p, 1e-3f, 1e9f);
    const int ozp = __ldg(ozp_p);

#pragma unroll
    for (int mt = 0; mt < 4; mt++) {
        const int row0 = bm + wm * 64 + mt * 16 + g;
#pragma unroll
        for (int nt = 0; nt < 4; nt++) {
            const int col0 = bn + wn * 32 + nt * 8 + t4 * 2;
            const float b0 = (float)g_bias[col0];
            const float b1 = (float)g_bias[col0 + 1];
            float2 lo, hi;
            lo.x = (float)clamp_i8((int)rintf((acc[mt][nt][0] + b0) / os) + ozp);
            lo.y = (float)clamp_i8((int)rintf((acc[mt][nt][1] + b1) / os) + ozp);
            hi.x = (float)clamp_i8((int)rintf((acc[mt][nt][2] + b0) / os) + ozp);
            hi.y = (float)clamp_i8((int)rintf((acc[mt][nt][3] + b1) / os) + ozp);
            *(float2*)&C[(size_t)row0 * N + col0]       = lo;
            *(float2*)&C[(size_t)(row0 + 8) * N + col0] = hi;
        }
    }
}

// ---------------------------------------------------------------------------
extern "C" void kernel_launch(void* const* d_in, const int* in_sizes, int n_in,
                              void* d_out, int out_size) {
    const float* input  = (const float*)d_in[0];
    const void*  weight = d_in[1];
    const void*  bias   = d_in[2];
    const void*  in_s   = d_in[3];
    const int*   in_zp  = (const int*)d_in[4];
    const void*  out_s  = d_in[5];
    const int*   out_zp = (const int*)d_in[6];

    const int N = in_sizes[2];
    const int K = in_sizes[1] / N;
    const int M = in_sizes[0] / K;

    float* out = (float*)d_out;

    int n4 = (M * K) / 4;
    quant_kernel<<<(n4 + 255) / 256, 256>>>((const float4*)input, in_s, in_zp, n4);

    int wn4 = (N * K) / 4;
    int tot = wn4 + N;
    convert_kernel<<<(tot + 255) / 256, 256>>>(weight, bias, wn4, N);

    cudaFuncSetAttribute(gemm_bf16_kernel,
                         cudaFuncAttributeMaxDynamicSharedMemorySize,
                         2 * STAGE_BYTES);
    dim3 grid(N / BN, M / BM);
    gemm_bf16_kernel<<<grid, 256, 2 * STAGE_BYTES>>>(out, M, N, K, out_s, out_zp);
}